// round 16
// baseline (speedup 1.0000x reference)
#include <cuda_runtime.h>
#include <stdint.h>
#include <math.h>

#define BATCH  512
#define TLEN   32768
#define NTH    64                    // 2 warps: w0 = compute, w1 = store
#define CHUNK  4096                  // samples per chunk (16 KB)
#define NCHUNK (TLEN / CHUNK)        // 8
#define NBUF   3
// 3 chunk buffers + 3 x 64 floats of entry states
#define SMEM_BYTES ((NBUF * CHUNK + 3 * 64) * 4)

#define BAR_SYNC(id)   asm volatile("bar.sync %0, 64;"   :: "r"(id) : "memory")
#define BAR_ARRIVE(id) asm volatile("bar.arrive %0, 64;" :: "r"(id) : "memory")

// ---------------------------------------------------------------------------
__device__ __forceinline__ void cp_async16(unsigned int dst, const float* src) {
    asm volatile("cp.async.cg.shared.global [%0], [%1], 16;\n" ::
                 "r"(dst), "l"(src));
}

// Swizzled layout: logical float4 f, owner row r = f>>5, k = f&31,
// stored at physical float4 r*32 + (k ^ r). Conflict-free both ways.
__device__ __forceinline__ void load_chunk(const float* __restrict__ g,
                                           unsigned int sbuf, int t) {
#pragma unroll
    for (int j = 0; j < 32; j++) {
        cp_async16(sbuf + (unsigned int)((j * 32 + (t ^ j)) * 16),
                   g + (j * 32 + t) * 4);
    }
    asm volatile("cp.async.commit_group;\n");
}

// ---------------------------------------------------------------------------
// One row per CTA, 2 warps: warp0 = loads + recurrence + scan,
// warp1 = correction + store.  Producer/consumer via named barriers.
// ---------------------------------------------------------------------------
__global__ void __launch_bounds__(NTH)
dsvf_ws_kernel(const float* __restrict__ x, float* __restrict__ out,
               const float* __restrict__ g_raw, const float* __restrict__ r_raw,
               const float* __restrict__ m_hp, const float* __restrict__ m_bp,
               const float* __restrict__ m_lp) {
    extern __shared__ float sm[];
    float* entry = sm + NBUF * CHUNK;     // [3][64] per-lane entry states
    const int tid = threadIdx.x;
    const int w = tid >> 5, t = tid & 31;

    const float* xrow = x + (size_t)blockIdx.x * TLEN;
    float* yrow = out + (size_t)blockIdx.x * TLEN;

    unsigned int sb[NBUF];
#pragma unroll
    for (int i = 0; i < NBUF; i++)
        sb[i] = (unsigned int)__cvta_generic_to_shared(sm + i * CHUNK);

    // compute warp prefetches chunks 0..2 before the (uniform) scalar setup
    if (w == 0) {
        load_chunk(xrow,             sb[0], t);
        load_chunk(xrow + CHUNK,     sb[1], t);
        load_chunk(xrow + 2 * CHUNK, sb[2], t);
    }

    // ---- coefficients (redundant in every lane of both warps) ----
    float sg = 1.0f / (1.0f + expf(-g_raw[0]));
    float gg = tanf(3.14159265358979323846f * sg * 0.5f);
    float rr = log1pf(expf(r_raw[0]));
    float g2 = gg * gg;
    float hp = m_hp[0], bp = m_bp[0], lp = m_lp[0];

    float b0 = g2 * lp + gg * bp + hp;
    float b1 = 2.0f * g2 * lp - 2.0f * hp;
    float b2 = g2 * lp - gg * bp + hp;
    float a0f = g2 + 2.0f * rr * gg + 1.0f;
    float a1 = 2.0f * g2 - 2.0f;
    float a2 = g2 - 2.0f * rr * gg + 1.0f;
    float inv = 1.0f / a0f;
    b0 *= inv; b1 *= inv; b2 *= inv; a1 *= inv; a2 *= inv;

    const float na1 = -a1;
    const float c1 = b1 - a1 * b0;        // input vector c of s' = A s + c x
    const float c2 = b2 - a2 * b0;

    double da1 = a1, da2 = a2, dc1 = c1, dc2 = c2;

    if (w == 0) {
        // =================== COMPUTE WARP ===================
        // pairwise (A^2) step constants
        const float A200 = (float)(da1 * da1 - da2);
        const float A201 = (float)(-da1);
        const float A210 = (float)(da1 * da2);
        const float A211 = (float)(-da2);
        const float d1   = (float)(-da1 * dc1 + dc2);   // (A c)_1
        const float d2   = (float)(-da2 * dc1);         // (A c)_2

        // Q[k] = A^(128 * 2^k), k = 0..4
        float Q[5][4];
        {
            double m00 = -da1, m01 = 1.0, m10 = -da2, m11 = 0.0;
#pragma unroll
            for (int i = 0; i < 7; i++) {
                double t00 = m00 * m00 + m01 * m10, t01 = m00 * m01 + m01 * m11;
                double t10 = m10 * m00 + m11 * m10, t11 = m10 * m01 + m11 * m11;
                m00 = t00; m01 = t01; m10 = t10; m11 = t11;
            }
            Q[0][0] = (float)m00; Q[0][1] = (float)m01;
            Q[0][2] = (float)m10; Q[0][3] = (float)m11;
#pragma unroll
            for (int k = 1; k < 5; k++) {
                double t00 = m00 * m00 + m01 * m10, t01 = m00 * m01 + m01 * m11;
                double t10 = m10 * m00 + m11 * m10, t11 = m10 * m01 + m11 * m11;
                m00 = t00; m01 = t01; m10 = t10; m11 = t11;
                Q[k][0] = (float)m00; Q[k][1] = (float)m01;
                Q[k][2] = (float)m10; Q[k][3] = (float)m11;
            }
        }

        float carry1 = 0.f, carry2 = 0.f;

#pragma unroll 1
        for (int c = 0; c < NCHUNK; c++) {
            const int b = c % NBUF;
            float* buf = sm + b * CHUNK;
            if (c < NCHUNK - 2)       asm volatile("cp.async.wait_group 2;\n");
            else if (c == NCHUNK - 2) asm volatile("cp.async.wait_group 1;\n");
            else                      asm volatile("cp.async.wait_group 0;\n");
            __syncwarp();

            float4* row = reinterpret_cast<float4*>(buf) + t * 32;

            // ---- single pass: zero-state recurrence, y0 in place ----
            float z1 = 0.f, z2 = 0.f;
#pragma unroll
            for (int k = 0; k < 32; k++) {
                float4 v = row[k ^ t];
                float4 o;
                {   // pair (v.x, v.y)
                    o.x = fmaf(b0, v.x, z1);
                    float u = fmaf(c1, v.x, z2);
                    o.y = fmaf(b0, v.y, fmaf(na1, z1, u));
                    float t1 = fmaf(d1, v.x, c1 * v.y);
                    float t2 = fmaf(d2, v.x, c2 * v.y);
                    float n1 = fmaf(A200, z1, fmaf(A201, z2, t1));
                    float n2 = fmaf(A210, z1, fmaf(A211, z2, t2));
                    z1 = n1; z2 = n2;
                }
                {   // pair (v.z, v.w)
                    o.z = fmaf(b0, v.z, z1);
                    float u = fmaf(c1, v.z, z2);
                    o.w = fmaf(b0, v.w, fmaf(na1, z1, u));
                    float t1 = fmaf(d1, v.z, c1 * v.w);
                    float t2 = fmaf(d2, v.z, c2 * v.w);
                    float n1 = fmaf(A200, z1, fmaf(A201, z2, t1));
                    float n2 = fmaf(A210, z1, fmaf(A211, z2, t2));
                    z1 = n1; z2 = n2;
                }
                row[k ^ t] = o;
            }

            // ---- warp scan with carry injected at lane 0 ----
            float s1 = z1, s2 = z2;
            if (t == 0) {
                s1 = fmaf(Q[0][0], carry1, fmaf(Q[0][1], carry2, s1));
                s2 = fmaf(Q[0][2], carry1, fmaf(Q[0][3], carry2, s2));
            }
#pragma unroll
            for (int d = 0; d < 5; d++) {
                int o = 1 << d;
                float u1 = __shfl_up_sync(0xffffffffu, s1, o);
                float u2 = __shfl_up_sync(0xffffffffu, s2, o);
                if (t >= o) {
                    s1 = fmaf(Q[d][0], u1, fmaf(Q[d][1], u2, s1));
                    s2 = fmaf(Q[d][2], u1, fmaf(Q[d][3], u2, s2));
                }
            }
            float p1 = __shfl_up_sync(0xffffffffu, s1, 1);
            float p2 = __shfl_up_sync(0xffffffffu, s2, 1);
            if (t == 0) { p1 = carry1; p2 = carry2; }
            carry1 = __shfl_sync(0xffffffffu, s1, 31);
            carry2 = __shfl_sync(0xffffffffu, s2, 31);

            entry[64 * b + 2 * t]     = p1;
            entry[64 * b + 2 * t + 1] = p2;
            __syncwarp();
            __threadfence_block();            // y0 + entry visible to warp 1
            BAR_ARRIVE(1 + b);                // ready(b)

            if (c + NBUF < NCHUNK) {
                BAR_SYNC(4 + b);              // wait store(c) freed buffer b
                load_chunk(xrow + (c + NBUF) * CHUNK, sb[b], t);
            }
        }
    } else {
        // =================== STORE WARP ===================
        // per-lane correction rows H: h(s) = e1^T A^s, s = 4t .. 4t+3
        float H1x, H1y, H1z, H1w, H2x, H2y, H2z, H2w;
        {
            double m00 = -da1, m01 = 1.0, m10 = -da2, m11 = 0.0;
#pragma unroll
            for (int i = 0; i < 2; i++) {     // A -> A^4
                double t00 = m00 * m00 + m01 * m10, t01 = m00 * m01 + m01 * m11;
                double t10 = m10 * m00 + m11 * m10, t11 = m10 * m01 + m11 * m11;
                m00 = t00; m01 = t01; m10 = t10; m11 = t11;
            }
            float P00 = (float)m00, P01 = (float)m01, P10 = (float)m10, P11 = (float)m11;
#pragma unroll
            for (int d = 0; d < 5; d++) {
                int o = 1 << d;
                float u00 = __shfl_up_sync(0xffffffffu, P00, o);
                float u01 = __shfl_up_sync(0xffffffffu, P01, o);
                float u10 = __shfl_up_sync(0xffffffffu, P10, o);
                float u11 = __shfl_up_sync(0xffffffffu, P11, o);
                if (t >= o) {
                    float n00 = P00 * u00 + P01 * u10, n01 = P00 * u01 + P01 * u11;
                    float n10 = P10 * u00 + P11 * u10, n11 = P10 * u01 + P11 * u11;
                    P00 = n00; P01 = n01; P10 = n10; P11 = n11;
                }
            }
            float e00 = __shfl_up_sync(0xffffffffu, P00, 1);
            float e01 = __shfl_up_sync(0xffffffffu, P01, 1);
            if (t == 0) { e00 = 1.f; e01 = 0.f; }
            float h1 = e00, h2 = e01;
            H1x = h1; H2x = h2;
            { float n = fmaf(na1, h1, -a2 * h2); h2 = h1; h1 = n; }
            H1y = h1; H2y = h2;
            { float n = fmaf(na1, h1, -a2 * h2); h2 = h1; h1 = n; }
            H1z = h1; H2z = h2;
            { float n = fmaf(na1, h1, -a2 * h2); h2 = h1; h1 = n; }
            H1w = h1; H2w = h2;
        }

#pragma unroll 1
        for (int c = 0; c < NCHUNK; c++) {
            const int b = c % NBUF;
            const float4* bb = reinterpret_cast<const float4*>(sm + b * CHUNK);
            const float* eb = entry + 64 * b;

            BAR_SYNC(1 + b);                  // wait ready(b)

            float4* go = reinterpret_cast<float4*>(yrow + c * CHUNK);
#pragma unroll
            for (int j = 0; j < 32; j++) {
                float4 v = bb[j * 32 + (t ^ j)];          // owner j, samples 4t..
                float e1 = eb[2 * j], e2 = eb[2 * j + 1]; // LDS broadcast
                float4 o;
                o.x = fmaf(H1x, e1, fmaf(H2x, e2, v.x));
                o.y = fmaf(H1y, e1, fmaf(H2y, e2, v.y));
                o.z = fmaf(H1z, e1, fmaf(H2z, e2, v.z));
                o.w = fmaf(H1w, e1, fmaf(H2w, e2, v.w));
                go[j * 32 + t] = o;
            }
            __syncwarp();
            BAR_ARRIVE(4 + b);                // free(b)
        }
    }
}

// ---------------------------------------------------------------------------
extern "C" void kernel_launch(void* const* d_in, const int* in_sizes, int n_in,
                              void* d_out, int out_size) {
    const float* x    = (const float*)d_in[0];
    const float* g    = (const float*)d_in[1];
    const float* r    = (const float*)d_in[2];
    const float* m_hp = (const float*)d_in[3];
    const float* m_bp = (const float*)d_in[4];
    const float* m_lp = (const float*)d_in[5];
    float* out = (float*)d_out;

    cudaFuncSetAttribute(dsvf_ws_kernel,
                         cudaFuncAttributeMaxDynamicSharedMemorySize, SMEM_BYTES);

    dsvf_ws_kernel<<<BATCH, NTH, SMEM_BYTES>>>(x, out, g, r, m_hp, m_bp, m_lp);
}